// round 16
// baseline (speedup 1.0000x reference)
#include <cuda_runtime.h>
#include <cuda_fp16.h>
#include <math.h>
#include <stdint.h>

// Problem constants
constexpr int T_ = 128, B_ = 32, L_ = 2, H_ = 1024, E_ = 1024, V_ = 32000;
constexpr int TB  = T_ * B_;     // 4096
constexpr int G4H = 4 * H_;      // 4096
constexpr int BH  = B_ * H_;     // 32768

constexpr int NBLK    = 128;     // persistent lstm blocks
constexpr int CO_BLKS = 20;      // co-op decoder blocks (SMs 128..147)
constexpr int CO_BM   = 4;       // decoder M-tiles handled in-kernel (bm 0..3)

// fp16 GEMM constants
constexpr int GEMM_SMEM = 3 * 32768;

// Fused LSTM smem (R12-proven): 3 W slices (64KB each) + 2 streams x 2 slots x 8KB
constexpr int SLOTS_OFF = 196608;
constexpr int LSTM_SMEM = 229376;

// Scratch (device globals)
__device__ float g_xproj[TB * G4H];                              // layer0 only
__device__ alignas(256) __half g_embhi[(size_t)TB * H_];         // 8.4MB hi
__device__ alignas(256) __half g_y0[(size_t)TB * H_];            // 8.4MB hi
__device__ alignas(256) __half g_y1[(size_t)TB * H_];            // 8.4MB hi
__device__ alignas(256) __half g_wih0hi[(size_t)G4H * H_];       // l0 hi plane
__device__ alignas(256) __half g_wih1hi[(size_t)G4H * H_];       // l1 hi plane
__device__ alignas(256) __half g_augdec[(size_t)V_ * H_];        // hi plane
__device__ alignas(256) __half g_whhaug[(size_t)L_ * G4H * H_];  // hi planes
__device__ alignas(256) __half g_h0aug[L_ * B_ * H_];            // [2][B][1024] hi

// barrier state: padded per-block monotonic flags (lstm blocks only)
__device__ unsigned g_flags[NBLK * 32];
// per-launch absolute round counters (reset to 0 after each lstm launch)
__device__ unsigned g_ready[NBLK * 32];

// ---------------------------------------------------------------------------
// Embedding gather -> fp16 hi plane
// ---------------------------------------------------------------------------
__global__ void embed_hi_kernel(const int* __restrict__ idx,
                                const float* __restrict__ emb,
                                __half* __restrict__ out) {
    int tb = blockIdx.x;
    int v  = idx[tb];
    int k4 = threadIdx.x << 2;
    float4 x = *(const float4*)(emb + (size_t)v * E_ + k4);
    __half h[4] = {__float2half_rn(x.x), __float2half_rn(x.y),
                   __float2half_rn(x.z), __float2half_rn(x.w)};
    unsigned long long hv;
    unsigned short* hp = (unsigned short*)&hv;
#pragma unroll
    for (int j = 0; j < 4; j++) hp[j] = *(unsigned short*)&h[j];
    *(unsigned long long*)(out + (size_t)tb * H_ + k4) = hv;
}

// hi-plane convert: fp32 [rows][1024] -> fp16 [rows][1024]
__global__ void hi_conv_kernel(const float* __restrict__ in,
                               __half* __restrict__ out) {
    int row = blockIdx.x;
    int k = threadIdx.x << 2;
    float4 v = *(const float4*)(in + (size_t)row * 1024 + k);
    __half h[4] = {__float2half_rn(v.x), __float2half_rn(v.y),
                   __float2half_rn(v.z), __float2half_rn(v.w)};
    unsigned long long hv;
    unsigned short* hp = (unsigned short*)&hv;
#pragma unroll
    for (int j = 0; j < 4; j++) hp[j] = *(unsigned short*)&h[j];
    *(unsigned long long*)(out + (size_t)row * 1024 + k) = hv;
}

// reset per-launch ready counters (runs after lstm each launch)
__global__ void reset_ready_kernel() {
    g_ready[threadIdx.x * 32] = 0u;
}

// ---------------------------------------------------------------------------
// low-level helpers
// ---------------------------------------------------------------------------
__device__ __forceinline__ uint32_t smem_u32(const void* p) {
    uint32_t a;
    asm("{ .reg .u64 t; cvta.to.shared.u64 t, %1; cvt.u32.u64 %0, t; }"
        : "=r"(a) : "l"(p));
    return a;
}
__device__ __forceinline__ void cp_async16(uint32_t saddr, const void* gptr) {
    asm volatile("cp.async.cg.shared.global [%0], [%1], 16;\n"
                 :: "r"(saddr), "l"(gptr));
}
__device__ __forceinline__ void cp_commit() {
    asm volatile("cp.async.commit_group;\n");
}
template <int N>
__device__ __forceinline__ void cp_wait() {
    asm volatile("cp.async.wait_group %0;\n" :: "n"(N));
}
__device__ __forceinline__ void ldsm4a(uint32_t* r, uint32_t a) {
    asm volatile("ldmatrix.sync.aligned.m8n8.x4.shared.b16 {%0,%1,%2,%3},[%4];"
                 : "=r"(r[0]), "=r"(r[1]), "=r"(r[2]), "=r"(r[3]) : "r"(a));
}
__device__ __forceinline__ void mma16816(float* c, const uint32_t* a,
                                         uint32_t b0, uint32_t b1) {
    asm volatile(
        "mma.sync.aligned.m16n8k16.row.col.f32.f16.f16.f32 "
        "{%0,%1,%2,%3},{%4,%5,%6,%7},{%8,%9},{%0,%1,%2,%3};"
        : "+f"(c[0]), "+f"(c[1]), "+f"(c[2]), "+f"(c[3])
        : "r"(a[0]), "r"(a[1]), "r"(a[2]), "r"(a[3]), "r"(b0), "r"(b1));
}
__device__ __forceinline__ float sigf(float x) { return 1.f / (1.f + expf(-x)); }

// ---------------------------------------------------------------------------
// GEMM tile body (128x128, K=1024, both operands row-major K-contig, lda=ldb=H)
// Shared by the standalone GEMM kernel and the in-lstm co-op decoder.
// ---------------------------------------------------------------------------
__device__ __forceinline__ void gemm_tile_1024(
        uint32_t smb, int tid,
        const __half* __restrict__ Ag, const __half* __restrict__ Bg,
        const float* __restrict__ bias, float* __restrict__ C,
        int rowBase, int colBase, int ldc) {
    const int lane = tid & 31;
    const int wid  = tid >> 5;
    const int wm   = wid >> 2;
    const int wn   = wid & 3;
    const int l7   = lane & 7;
    const int l8   = (lane >> 3) & 1;
    const int l16  = lane >> 4;
    const int KT   = 16;

    auto issue = [&](int kt, int st) {
        uint32_t sa = smb + st * 32768;
#pragma unroll
        for (int j = 0; j < 8; j++) {
            int id  = tid + (j & 3) * 256;
            int row = id >> 3, c = id & 7;
            uint32_t dst = sa + (j < 4 ? 0u : 16384u)
                         + (uint32_t)(row * 128 + ((c ^ (row & 7)) << 4));
            const __half* src = (j < 4 ? Ag : Bg) + (size_t)row * H_ + kt * 64 + c * 8;
            cp_async16(dst, src);
        }
        cp_commit();
    };

    float acc[4][4][4];
#pragma unroll
    for (int i = 0; i < 4; i++)
#pragma unroll
        for (int j = 0; j < 4; j++)
#pragma unroll
            for (int k = 0; k < 4; k++) acc[i][j][k] = 0.f;

    issue(0, 0);
    issue(1, 1);

    uint32_t aRow[4], bRowP[2];
#pragma unroll
    for (int mt = 0; mt < 4; mt++)
        aRow[mt] = (uint32_t)((wm * 64 + mt * 16 + l7 + l8 * 8) * 128);
#pragma unroll
    for (int ntp = 0; ntp < 2; ntp++)
        bRowP[ntp] = (uint32_t)(16384 + (wn * 32 + ntp * 16 + l16 * 8 + l7) * 128);

    for (int kt = 0; kt < KT; kt++) {
        if (kt + 1 < KT) cp_wait<1>(); else cp_wait<0>();
        __syncthreads();
        if (kt + 2 < KT) issue(kt + 2, (kt + 2) % 3);

        uint32_t st = smb + (kt % 3) * 32768;
#pragma unroll
        for (int kq = 0; kq < 4; kq++) {
            uint32_t aF[4][4], bQ[2][4];
            uint32_t ach = (uint32_t)((((kq * 2 + l16) ^ l7)) << 4);
#pragma unroll
            for (int mt = 0; mt < 4; mt++)
                ldsm4a(aF[mt], st + aRow[mt] + ach);
            uint32_t bch = (uint32_t)((((kq * 2 + l8) ^ l7)) << 4);
            ldsm4a(bQ[0], st + bRowP[0] + bch);
            ldsm4a(bQ[1], st + bRowP[1] + bch);
#pragma unroll
            for (int mt = 0; mt < 4; mt++)
#pragma unroll
                for (int nt = 0; nt < 4; nt++)
                    mma16816(acc[mt][nt], aF[mt],
                             bQ[nt >> 1][(nt & 1) * 2],
                             bQ[nt >> 1][(nt & 1) * 2 + 1]);
        }
    }

    const int gid = lane >> 2, tig = lane & 3;
#pragma unroll
    for (int mt = 0; mt < 4; mt++) {
        int row0 = rowBase + wm * 64 + mt * 16 + gid;
#pragma unroll
        for (int nt = 0; nt < 4; nt++) {
            int col = colBase + wn * 32 + nt * 8 + tig * 2;
            float b0 = bias[col], b1 = bias[col + 1];
            *(float2*)(C + (size_t)row0 * ldc + col) =
                make_float2(acc[mt][nt][0] + b0, acc[mt][nt][1] + b1);
            *(float2*)(C + (size_t)(row0 + 8) * ldc + col) =
                make_float2(acc[mt][nt][2] + b0, acc[mt][nt][3] + b1);
        }
    }
}

// ---------------------------------------------------------------------------
// fp16 mma.sync GEMM (proven config): C = A[.., lda] @ B[N,K]^T + bias1+bias2
// bm = bmOff + bid % bmDiv, bn = bid / bmDiv.
// ---------------------------------------------------------------------------
__global__ __launch_bounds__(256, 2)
void gemm_fp16_mma(const __half* __restrict__ A, const __half* __restrict__ B,
                   const float* __restrict__ bias1, const float* __restrict__ bias2,
                   float* __restrict__ C, int K, int lda, int ldc,
                   int bmOff, int bmDiv) {
    extern __shared__ char sm[];
    const int tid  = threadIdx.x;
    const int lane = tid & 31;
    const int wid  = tid >> 5;
    const int bm   = bmOff + (int)(blockIdx.x % bmDiv);
    const int bn   = (int)(blockIdx.x / bmDiv);
    const int wm   = wid >> 2;
    const int wn   = wid & 3;
    const uint32_t smb = smem_u32(sm);
    const int KT = K >> 6;

    const __half* Ag = A + (size_t)(bm * 128) * lda;
    const __half* Bg = B + (size_t)(bn * 128) * K;

    auto issue = [&](int kt, int st) {
        uint32_t sa = smb + st * 32768;
#pragma unroll
        for (int j = 0; j < 8; j++) {
            int id  = tid + (j & 3) * 256;
            int row = id >> 3, c = id & 7;
            uint32_t dst = sa + (j < 4 ? 0u : 16384u)
                         + (uint32_t)(row * 128 + ((c ^ (row & 7)) << 4));
            const __half* src = (j < 4)
                ? Ag + (size_t)row * lda + kt * 64 + c * 8
                : Bg + (size_t)row * K   + kt * 64 + c * 8;
            cp_async16(dst, src);
        }
        cp_commit();
    };

    float acc[4][4][4];
#pragma unroll
    for (int i = 0; i < 4; i++)
#pragma unroll
        for (int j = 0; j < 4; j++)
#pragma unroll
            for (int k = 0; k < 4; k++) acc[i][j][k] = 0.f;

    issue(0, 0);
    issue(1, 1);

    const int l7  = lane & 7;
    const int l8  = (lane >> 3) & 1;
    const int l16 = lane >> 4;

    uint32_t aRow[4], bRowP[2];
#pragma unroll
    for (int mt = 0; mt < 4; mt++)
        aRow[mt] = (uint32_t)((wm * 64 + mt * 16 + l7 + l8 * 8) * 128);
#pragma unroll
    for (int ntp = 0; ntp < 2; ntp++)
        bRowP[ntp] = (uint32_t)(16384 + (wn * 32 + ntp * 16 + l16 * 8 + l7) * 128);

    for (int kt = 0; kt < KT; kt++) {
        if (kt + 1 < KT) cp_wait<1>(); else cp_wait<0>();
        __syncthreads();
        if (kt + 2 < KT) issue(kt + 2, (kt + 2) % 3);

        uint32_t st = smb + (kt % 3) * 32768;
#pragma unroll
        for (int kq = 0; kq < 4; kq++) {
            uint32_t aF[4][4], bQ[2][4];
            uint32_t ach = (uint32_t)((((kq * 2 + l16) ^ l7)) << 4);
#pragma unroll
            for (int mt = 0; mt < 4; mt++)
                ldsm4a(aF[mt], st + aRow[mt] + ach);
            uint32_t bch = (uint32_t)((((kq * 2 + l8) ^ l7)) << 4);
            ldsm4a(bQ[0], st + bRowP[0] + bch);
            ldsm4a(bQ[1], st + bRowP[1] + bch);
#pragma unroll
            for (int mt = 0; mt < 4; mt++)
#pragma unroll
                for (int nt = 0; nt < 4; nt++)
                    mma16816(acc[mt][nt], aF[mt],
                             bQ[nt >> 1][(nt & 1) * 2],
                             bQ[nt >> 1][(nt & 1) * 2 + 1]);
        }
    }

    const int gid = lane >> 2, tig = lane & 3;
#pragma unroll
    for (int mt = 0; mt < 4; mt++) {
        int row0 = bm * 128 + wm * 64 + mt * 16 + gid;
#pragma unroll
        for (int nt = 0; nt < 4; nt++) {
            int col = bn * 128 + wn * 32 + nt * 8 + tig * 2;
            float b0 = bias1 ? bias1[col] : 0.f;
            float b1 = bias1 ? bias1[col + 1] : 0.f;
            if (bias2) { b0 += bias2[col]; b1 += bias2[col + 1]; }
            *(float2*)(C + (size_t)row0 * ldc + col) =
                make_float2(acc[mt][nt][0] + b0, acc[mt][nt][1] + b1);
            *(float2*)(C + (size_t)(row0 + 8) * ldc + col) =
                make_float2(acc[mt][nt][2] + b0, acc[mt][nt][3] + b1);
        }
    }
}

// ---------------------------------------------------------------------------
// Fused 2-layer persistent LSTM + co-op decoder blocks.
// Blocks 0..127: wavefront recurrence (R14-proven structure/barrier).
// Blocks 128..147: decoder tiles bm<CO_BM, gated on g_ready (y1 readiness).
// ---------------------------------------------------------------------------
__global__ __launch_bounds__(256, 1)
void lstm_fused(const float* __restrict__ xproj,    // [T*B][4H] layer0
                const __half* __restrict__ w0,      // W_hh0 hi [4H][1024]
                const __half* __restrict__ w1x,     // W_ih1 hi [4H][1024]
                const __half* __restrict__ w1h,     // W_hh1 hi [4H][1024]
                const float* __restrict__ c0,       // [2][B][H]
                const float* __restrict__ b_ih,     // [2][4H]
                const float* __restrict__ b_hh,     // [2][4H]
                const __half* __restrict__ h0a,     // [2][B][1024] hi
                __half* __restrict__ y0,            // [T*B][1024] hi
                __half* __restrict__ y1,            // [T*B][1024] hi
                float* __restrict__ outs,           // hs[2][B][H], cs[2][B][H]
                const __half* __restrict__ dec_w,   // [V][1024] hi
                const float* __restrict__ dec_b,    // [V]
                float* __restrict__ dec_out) {      // [T*B][V]
    extern __shared__ char dsm[];
    __shared__ unsigned s_base;

    const int tid  = threadIdx.x;
    const int blk  = blockIdx.x;
    const int wid  = tid >> 5;
    const int lane = tid & 31;
    const uint32_t smb = smem_u32(dsm);

    // ------------------- co-op decoder path (blocks >= NBLK) -------------------
    if (blk >= NBLK) {
        const int cid = blk - NBLK;
        volatile unsigned* rdy = g_ready;
        int lastNeed = -1;
        for (int tt = cid; tt < CO_BM * 250; tt += CO_BLKS) {
            int bm = tt / 250;
            int bn = tt % 250;
            int need = 4 * bm + 5;   // y1[t<=4bm+3] published at round t+1
            if (need > lastNeed) {
                if (wid == 0) {
                    for (;;) {
                        int ok = 1;
#pragma unroll
                        for (int j = 0; j < 4; j++) {
                            unsigned v = rdy[(lane + 32 * j) * 32];
                            if ((int)v < need) ok = 0;
                        }
                        if (__all_sync(0xffffffffu, ok)) break;
                        __nanosleep(64);
                    }
                }
                __syncthreads();
                lastNeed = need;
            }
            gemm_tile_1024(smb, tid,
                           y1 + (size_t)(bm * 128) * H_,
                           dec_w + (size_t)(bn * 128) * H_,
                           dec_b, dec_out, bm * 128, bn * 128, V_);
            __syncthreads();
        }
        return;
    }

    // ------------------- lstm path (blocks 0..127) -------------------
    const int n0   = blk * 8;
    const int l7   = lane & 7;
    const int l16  = lane >> 4;
    const int g2   = (lane >> 3) & 3;
    const int gid  = lane >> 2;
    const int tig  = lane & 3;
    const int mt   = wid >> 2;          // batch half
    const int nt   = wid & 3;           // gate
    const int b2   = tid >> 3;          // phase2 batch
    const int u2   = tid & 7;           // phase2 unit

    // load 3 weight slices (32 rows x 1024 each) into swizzled chunk layout
    for (int idx = tid; idx < 3 * 4096; idx += 256) {
        int m   = idx >> 12;
        int rem = idx & 4095;
        int ci  = rem >> 8;
        int rr  = (rem >> 3) & 31;
        int c   = rem & 7;
        uint32_t dst = (uint32_t)(m * 65536 + ci * 4096 + rr * 128
                                  + ((c ^ (rr & 7)) << 4));
        int gr = (rr >> 3) * H_ + n0 + (rr & 7);
        const __half* src = (m == 0 ? w0 : (m == 1 ? w1x : w1h))
                          + (size_t)gr * H_ + ci * 64 + c * 8;
        *(float4*)(dsm + dst) = *(const float4*)src;
    }

    if (tid == 0) s_base = *(volatile unsigned*)&g_flags[blk * 32];

    float c_reg0 = c0[b2 * H_ + n0 + u2];
    float c_reg1 = c0[BH + b2 * H_ + n0 + u2];
    float bi1[4];
#pragma unroll
    for (int g = 0; g < 4; g++)
        bi1[g] = b_ih[G4H + g * H_ + n0 + u2] + b_hh[G4H + g * H_ + n0 + u2];

    __syncthreads();
    const unsigned base = s_base;

    const uint32_t aRow128 = (uint32_t)((mt * 16 + l7 + ((lane >> 3) & 1) * 8) * 128);
    const uint32_t bRow128 = (uint32_t)((nt * 8 + l7) * 128);

    for (int r = 0; r <= T_; ++r) {
        const __half* Asrc = (r == 0) ? h0a : y0 + (size_t)(r - 1) * B_ * H_;
        const __half* Bsrc = (r <= 1) ? (h0a + (size_t)B_ * H_)
                                      : y1 + (size_t)(r - 2) * B_ * H_;

        // prefetch xproj0 gate values (clamped at r=T_, discarded)
        int tx = (r < T_) ? r : (T_ - 1);
        const float* xp = xproj + ((size_t)tx * B_ + b2) * G4H + n0 + u2;
        float xpi = __ldcg(xp);
        float xpf = __ldcg(xp + H_);
        float xpg = __ldcg(xp + 2 * H_);
        float xpo = __ldcg(xp + 3 * H_);

        auto issue_slot = [&](int i) {
            int k0 = i * 128;
            int row = tid >> 3, c = tid & 7;
            uint32_t sw = (uint32_t)(row * 128 + ((c ^ (row & 7)) << 4));
            uint32_t sbA = smb + SLOTS_OFF + (uint32_t)((i & 1) * 8192);
            uint32_t sbB = sbA + 16384u;
#pragma unroll
            for (int cc = 0; cc < 2; cc++) {
                cp_async16(sbA + cc * 4096 + sw,
                           Asrc + (size_t)row * H_ + k0 + cc * 64 + c * 8);
                cp_async16(sbB + cc * 4096 + sw,
                           Bsrc + (size_t)row * H_ + k0 + cc * 64 + c * 8);
            }
            cp_commit();
        };

        float acc0[4] = {0.f, 0.f, 0.f, 0.f};
        float acc1[4] = {0.f, 0.f, 0.f, 0.f};

        issue_slot(0); issue_slot(1);

#pragma unroll 1
        for (int i = 0; i < 8; i++) {
            if (i < 7) cp_wait<1>(); else cp_wait<0>();
            __syncthreads();

            uint32_t slotA = smb + SLOTS_OFF + (uint32_t)((i & 1) * 8192);
            uint32_t slotB = slotA + 16384u;
            int ciBase = i * 2;
#pragma unroll
            for (int cc = 0; cc < 2; cc++) {
                uint32_t wB0  = smb + (uint32_t)((ciBase + cc) * 4096);
                uint32_t wB1x = wB0 + 65536u;
                uint32_t wB1h = wB0 + 131072u;
                uint32_t hA = slotA + (uint32_t)(cc * 4096);
                uint32_t hB = slotB + (uint32_t)(cc * 4096);
#pragma unroll
                for (int kq2 = 0; kq2 < 2; kq2++) {
                    uint32_t bOff = bRow128 + (uint32_t)((((kq2 * 4 + g2) ^ l7)) << 4);
                    uint32_t aO0  = (uint32_t)((((kq2 * 4 + l16) ^ l7)) << 4);
                    uint32_t aO1  = (uint32_t)((((kq2 * 4 + 2 + l16) ^ l7)) << 4);
                    uint32_t a0[4], a1[4], bb0[4], bb1[4], w[4];
                    ldsm4a(a0, hA + aRow128 + aO0);
                    ldsm4a(a1, hA + aRow128 + aO1);
                    ldsm4a(w, wB0 + bOff);
                    mma16816(acc0, a0, w[0], w[1]);
                    mma16816(acc0, a1, w[2], w[3]);
                    ldsm4a(w, wB1x + bOff);
                    mma16816(acc1, a0, w[0], w[1]);
                    mma16816(acc1, a1, w[2], w[3]);
                    ldsm4a(bb0, hB + aRow128 + aO0);
                    ldsm4a(bb1, hB + aRow128 + aO1);
                    ldsm4a(w, wB1h + bOff);
                    mma16816(acc1, bb0, w[0], w[1]);
                    mma16816(acc1, bb1, w[2], w[3]);
                }
            }
            __syncthreads();
            if (i + 2 < 8) issue_slot(i + 2);
        }

        // gates to smem (overlay on slot region; all slot reads done)
        float* sg0 = (float*)(dsm + SLOTS_OFF);
        float* sg1 = sg0 + 1024;
        {
            int row = mt * 16 + gid;
            sg0[nt * 256 + row * 8 + tig * 2]           = acc0[0];
            sg0[nt * 256 + row * 8 + tig * 2 + 1]       = acc0[1];
            sg0[nt * 256 + (row + 8) * 8 + tig * 2]     = acc0[2];
            sg0[nt * 256 + (row + 8) * 8 + tig * 2 + 1] = acc0[3];
            sg1[nt * 256 + row * 8 + tig * 2]           = acc1[0];
            sg1[nt * 256 + row * 8 + tig * 2 + 1]       = acc1[1];
            sg1[nt * 256 + (row + 8) * 8 + tig * 2]     = acc1[2];
            sg1[nt * 256 + (row + 8) * 8 + tig * 2 + 1] = acc1[3];
        }
        __syncthreads();

        // phase 2: layer 0 (t = r)
        if (r < T_) {
            float gi = sg0[0 * 256 + b2 * 8 + u2] + xpi;
            float gf = sg0[1 * 256 + b2 * 8 + u2] + xpf;
            float gg = sg0[2 * 256 + b2 * 8 + u2] + xpg;
            float go = sg0[3 * 256 + b2 * 8 + u2] + xpo;
            float iv = sigf(gi), fv = sigf(gf), gv = tanhf(gg), ov = sigf(go);
            c_reg0 = fv * c_reg0 + iv * gv;
            float h = ov * tanhf(c_reg0);
            y0[((size_t)r * B_ + b2) * H_ + n0 + u2] = __float2half_rn(h);
            if (r == T_ - 1) {
                outs[b2 * H_ + n0 + u2]          = h;        // hs[0]
                outs[2 * BH + b2 * H_ + n0 + u2] = c_reg0;   // cs[0]
            }
        }
        // phase 2: layer 1 (t = r-1)
        if (r >= 1) {
            int t = r - 1;
            float gi = sg1[0 * 256 + b2 * 8 + u2] + bi1[0];
            float gf = sg1[1 * 256 + b2 * 8 + u2] + bi1[1];
            float gg = sg1[2 * 256 + b2 * 8 + u2] + bi1[2];
            float go = sg1[3 * 256 + b2 * 8 + u2] + bi1[3];
            float iv = sigf(gi), fv = sigf(gf), gv = tanhf(gg), ov = sigf(go);
            c_reg1 = fv * c_reg1 + iv * gv;
            float h = ov * tanhf(c_reg1);
            y1[((size_t)t * B_ + b2) * H_ + n0 + u2] = __float2half_rn(h);
            if (t == T_ - 1) {
                outs[BH + b2 * H_ + n0 + u2]     = h;        // hs[1]
                outs[3 * BH + b2 * H_ + n0 + u2] = c_reg1;   // cs[1]
            }
        }

        // distributed barrier: publish flag + round counter, poll all flags
        __syncthreads();
        unsigned tgt = base + (unsigned)(r + 1);
        if (tid == 0) {
            __threadfence();
            *(volatile unsigned*)&g_flags[blk * 32] = tgt;
            *(volatile unsigned*)&g_ready[blk * 32] = (unsigned)(r + 1);
        }
        if (wid == 0) {
            volatile unsigned* fl = g_flags;
            for (;;) {
                int ok = 1;
#pragma unroll
                for (int j = 0; j < 4; j++) {
                    unsigned v = fl[(lane + 32 * j) * 32];
                    if ((int)(v - tgt) < 0) ok = 0;
                }
                if (__all_sync(0xffffffffu, ok)) break;
                __nanosleep(16);
            }
            __threadfence();
        }
        __syncthreads();
    }
}

// ---------------------------------------------------------------------------
// Launch
// ---------------------------------------------------------------------------
extern "C" void kernel_launch(void* const* d_in, const int* in_sizes, int n_in,
                              void* d_out, int out_size) {
    const int*   input = (const int*)d_in[0];
    const float* h0    = (const float*)d_in[1];
    const float* c0    = (const float*)d_in[2];
    const float* emb   = (const float*)d_in[3];
    const float* W_ih  = (const float*)d_in[4];
    const float* W_hh  = (const float*)d_in[5];
    const float* b_ih  = (const float*)d_in[6];
    const float* b_hh  = (const float*)d_in[7];
    const float* dec_W = (const float*)d_in[8];
    const float* dec_b = (const float*)d_in[9];
    float* out = (float*)d_out;

    void* p;
    cudaGetSymbolAddress(&p, g_xproj);  float* xproj = (float*)p;
    cudaGetSymbolAddress(&p, g_embhi);  __half* embhi = (__half*)p;
    cudaGetSymbolAddress(&p, g_y0);     __half* y0 = (__half*)p;
    cudaGetSymbolAddress(&p, g_y1);     __half* y1 = (__half*)p;
    cudaGetSymbolAddress(&p, g_wih0hi); __half* wih0hi = (__half*)p;
    cudaGetSymbolAddress(&p, g_wih1hi); __half* wih1hi = (__half*)p;
    cudaGetSymbolAddress(&p, g_augdec); __half* augdec = (__half*)p;
    cudaGetSymbolAddress(&p, g_whhaug); __half* whhaug = (__half*)p;
    cudaGetSymbolAddress(&p, g_h0aug);  __half* h0aug = (__half*)p;

    cudaFuncSetAttribute(gemm_fp16_mma,
                         cudaFuncAttributeMaxDynamicSharedMemorySize, GEMM_SMEM);
    cudaFuncSetAttribute(lstm_fused,
                         cudaFuncAttributeMaxDynamicSharedMemorySize, LSTM_SMEM);

    // 1) embedding + weight conversions + initial states (all hi-plane)
    embed_hi_kernel<<<TB, 256>>>(input, emb, embhi);
    hi_conv_kernel<<<V_, 256>>>(dec_W, augdec);                   // decoder hi
    hi_conv_kernel<<<G4H, 256>>>(W_ih, wih0hi);                   // l0 hi
    hi_conv_kernel<<<G4H, 256>>>(W_ih + (size_t)G4H * E_, wih1hi);// l1 hi
    hi_conv_kernel<<<L_ * G4H, 256>>>(W_hh, whhaug);              // hh hi
    hi_conv_kernel<<<L_ * B_, 256>>>(h0, h0aug);                  // h0 hi

    const size_t D0 = (size_t)TB * V_;

    // 2) layer0 input projection: hi-only, K=1024
    gemm_fp16_mma<<<(G4H / 128) * 32, 256, GEMM_SMEM>>>(
        embhi, wih0hi, b_ih, b_hh, xproj, H_, H_, G4H, 0, 32);

    // 3) fused 2-layer recurrence + co-op decoder (bm < CO_BM) in one launch
    lstm_fused<<<NBLK + CO_BLKS, 256, LSTM_SMEM>>>(
        xproj, whhaug, wih1hi, whhaug + (size_t)G4H * H_,
        c0, b_ih, b_hh, h0aug, y0, y1, out + D0,
        augdec, dec_b, out);

    // 3b) reset per-launch ready counters (graph replay determinism)
    reset_ready_kernel<<<1, NBLK>>>();

    // 4) decoder tail: bm = CO_BM..31
    gemm_fp16_mma<<<(32 - CO_BM) * 250, 256, GEMM_SMEM>>>(
        y1, augdec, dec_b, nullptr, out, H_, H_, V_, CO_BM, 32 - CO_BM);
}

// round 17
// speedup vs baseline: 1.4178x; 1.4178x over previous
#include <cuda_runtime.h>
#include <cuda_fp16.h>
#include <math.h>
#include <stdint.h>

// Problem constants
constexpr int T_ = 128, B_ = 32, L_ = 2, H_ = 1024, E_ = 1024, V_ = 32000;
constexpr int TB  = T_ * B_;     // 4096
constexpr int G4H = 4 * H_;      // 4096
constexpr int BH  = B_ * H_;     // 32768

constexpr int NBLK = 128;        // persistent blocks, 8 units x 2 layers each

// fp16 GEMM constants
constexpr int GEMM_SMEM = 3 * 32768;

// Fused LSTM smem (R12-proven): 3 W slices (64KB each) + 2 streams x 2 slots x 8KB
constexpr int SLOTS_OFF = 196608;
constexpr int LSTM_SMEM = 229376;

// Scratch (device globals)
__device__ float g_xproj[TB * G4H];                              // layer0 only
__device__ alignas(256) __half g_embhi[(size_t)TB * H_];         // 8.4MB hi
__device__ alignas(256) __half g_y0[(size_t)TB * H_];            // 8.4MB hi
__device__ alignas(256) __half g_y1[(size_t)TB * H_];            // 8.4MB hi
__device__ alignas(256) __half g_wih0hi[(size_t)G4H * H_];       // l0 hi plane
__device__ alignas(256) __half g_wih1hi[(size_t)G4H * H_];       // l1 hi plane
__device__ alignas(256) __half g_augdec[(size_t)V_ * H_];        // hi plane
__device__ alignas(256) __half g_whhaug[(size_t)L_ * G4H * H_];  // hi planes
__device__ alignas(256) __half g_h0aug[L_ * B_ * H_];            // [2][B][1024] hi

// barrier state: padded per-block monotonic flags
__device__ unsigned g_flags[NBLK * 32];

// ---------------------------------------------------------------------------
// Unified prep: embed-gather + all fp32->fp16 hi-plane conversions, ONE launch.
// Block ranges: [0,TB) embed | [TB,+V) dec_W | +G4H wih0 | +G4H wih1
//               | +2*G4H whh | +L*B h0
// Each block converts one 1024-float row with 256 threads.
// ---------------------------------------------------------------------------
constexpr int PREP_BLKS = TB + V_ + G4H + G4H + L_ * G4H + L_ * B_;  // 52544

__global__ void prep_kernel(const int* __restrict__ idx,
                            const float* __restrict__ emb,
                            const float* __restrict__ dec_W,
                            const float* __restrict__ W_ih,
                            const float* __restrict__ W_hh,
                            const float* __restrict__ h0,
                            __half* __restrict__ embhi,
                            __half* __restrict__ augdec,
                            __half* __restrict__ wih0hi,
                            __half* __restrict__ wih1hi,
                            __half* __restrict__ whhaug,
                            __half* __restrict__ h0aug) {
    int b = blockIdx.x;
    const float* src;
    __half* dst;

    if (b < TB) {                                  // embedding gather
        int v = idx[b];
        src = emb + (size_t)v * E_;
        dst = embhi + (size_t)b * H_;
    } else if ((b -= TB) < V_) {                   // decoder weight
        src = dec_W + (size_t)b * H_;
        dst = augdec + (size_t)b * H_;
    } else if ((b -= V_) < G4H) {                  // W_ih layer 0
        src = W_ih + (size_t)b * H_;
        dst = wih0hi + (size_t)b * H_;
    } else if ((b -= G4H) < G4H) {                 // W_ih layer 1
        src = W_ih + (size_t)(G4H + b) * H_;
        dst = wih1hi + (size_t)b * H_;
    } else if ((b -= G4H) < L_ * G4H) {            // W_hh both layers
        src = W_hh + (size_t)b * H_;
        dst = whhaug + (size_t)b * H_;
    } else {                                       // h0 both layers
        b -= L_ * G4H;
        src = h0 + (size_t)b * H_;
        dst = h0aug + (size_t)b * H_;
    }

    int k = threadIdx.x << 2;
    float4 v = *(const float4*)(src + k);
    __half h[4] = {__float2half_rn(v.x), __float2half_rn(v.y),
                   __float2half_rn(v.z), __float2half_rn(v.w)};
    unsigned long long hv;
    unsigned short* hp = (unsigned short*)&hv;
#pragma unroll
    for (int j = 0; j < 4; j++) hp[j] = *(unsigned short*)&h[j];
    *(unsigned long long*)(dst + k) = hv;
}

// ---------------------------------------------------------------------------
// low-level helpers
// ---------------------------------------------------------------------------
__device__ __forceinline__ uint32_t smem_u32(const void* p) {
    uint32_t a;
    asm("{ .reg .u64 t; cvta.to.shared.u64 t, %1; cvt.u32.u64 %0, t; }"
        : "=r"(a) : "l"(p));
    return a;
}
__device__ __forceinline__ void cp_async16(uint32_t saddr, const void* gptr) {
    asm volatile("cp.async.cg.shared.global [%0], [%1], 16;\n"
                 :: "r"(saddr), "l"(gptr));
}
__device__ __forceinline__ void cp_commit() {
    asm volatile("cp.async.commit_group;\n");
}
template <int N>
__device__ __forceinline__ void cp_wait() {
    asm volatile("cp.async.wait_group %0;\n" :: "n"(N));
}
__device__ __forceinline__ void ldsm4a(uint32_t* r, uint32_t a) {
    asm volatile("ldmatrix.sync.aligned.m8n8.x4.shared.b16 {%0,%1,%2,%3},[%4];"
                 : "=r"(r[0]), "=r"(r[1]), "=r"(r[2]), "=r"(r[3]) : "r"(a));
}
__device__ __forceinline__ void mma16816(float* c, const uint32_t* a,
                                         uint32_t b0, uint32_t b1) {
    asm volatile(
        "mma.sync.aligned.m16n8k16.row.col.f32.f16.f16.f32 "
        "{%0,%1,%2,%3},{%4,%5,%6,%7},{%8,%9},{%0,%1,%2,%3};"
        : "+f"(c[0]), "+f"(c[1]), "+f"(c[2]), "+f"(c[3])
        : "r"(a[0]), "r"(a[1]), "r"(a[2]), "r"(a[3]), "r"(b0), "r"(b1));
}
__device__ __forceinline__ float sigf(float x) { return 1.f / (1.f + expf(-x)); }

// ---------------------------------------------------------------------------
// fp16 mma.sync GEMM (proven config): C = A[.., lda] @ B[N,K]^T + bias
// ---------------------------------------------------------------------------
__global__ __launch_bounds__(256, 2)
void gemm_fp16_mma(const __half* __restrict__ A, const __half* __restrict__ B,
                   const float* __restrict__ bias1, const float* __restrict__ bias2,
                   float* __restrict__ C, int K, int lda, int ldc) {
    extern __shared__ char sm[];
    const int tid  = threadIdx.x;
    const int lane = tid & 31;
    const int wid  = tid >> 5;
    const int bm   = blockIdx.x & 31;
    const int bn   = blockIdx.x >> 5;
    const int wm   = wid >> 2;
    const int wn   = wid & 3;
    const uint32_t smb = smem_u32(sm);
    const int KT = K >> 6;

    const __half* Ag = A + (size_t)(bm * 128) * lda;
    const __half* Bg = B + (size_t)(bn * 128) * K;

    auto issue = [&](int kt, int st) {
        uint32_t sa = smb + st * 32768;
#pragma unroll
        for (int j = 0; j < 8; j++) {
            int id  = tid + (j & 3) * 256;
            int row = id >> 3, c = id & 7;
            uint32_t dst = sa + (j < 4 ? 0u : 16384u)
                         + (uint32_t)(row * 128 + ((c ^ (row & 7)) << 4));
            const __half* src = (j < 4)
                ? Ag + (size_t)row * lda + kt * 64 + c * 8
                : Bg + (size_t)row * K   + kt * 64 + c * 8;
            cp_async16(dst, src);
        }
        cp_commit();
    };

    float acc[4][4][4];
#pragma unroll
    for (int i = 0; i < 4; i++)
#pragma unroll
        for (int j = 0; j < 4; j++)
#pragma unroll
            for (int k = 0; k < 4; k++) acc[i][j][k] = 0.f;

    issue(0, 0);
    issue(1, 1);

    const int l7  = lane & 7;
    const int l8  = (lane >> 3) & 1;
    const int l16 = lane >> 4;

    uint32_t aRow[4], bRowP[2];
#pragma unroll
    for (int mt = 0; mt < 4; mt++)
        aRow[mt] = (uint32_t)((wm * 64 + mt * 16 + l7 + l8 * 8) * 128);
#pragma unroll
    for (int ntp = 0; ntp < 2; ntp++)
        bRowP[ntp] = (uint32_t)(16384 + (wn * 32 + ntp * 16 + l16 * 8 + l7) * 128);

    for (int kt = 0; kt < KT; kt++) {
        if (kt + 1 < KT) cp_wait<1>(); else cp_wait<0>();
        __syncthreads();
        if (kt + 2 < KT) issue(kt + 2, (kt + 2) % 3);

        uint32_t st = smb + (kt % 3) * 32768;
#pragma unroll
        for (int kq = 0; kq < 4; kq++) {
            uint32_t aF[4][4], bQ[2][4];
            uint32_t ach = (uint32_t)((((kq * 2 + l16) ^ l7)) << 4);
#pragma unroll
            for (int mt = 0; mt < 4; mt++)
                ldsm4a(aF[mt], st + aRow[mt] + ach);
            uint32_t bch = (uint32_t)((((kq * 2 + l8) ^ l7)) << 4);
            ldsm4a(bQ[0], st + bRowP[0] + bch);
            ldsm4a(bQ[1], st + bRowP[1] + bch);
#pragma unroll
            for (int mt = 0; mt < 4; mt++)
#pragma unroll
                for (int nt = 0; nt < 4; nt++)
                    mma16816(acc[mt][nt], aF[mt],
                             bQ[nt >> 1][(nt & 1) * 2],
                             bQ[nt >> 1][(nt & 1) * 2 + 1]);
        }
    }

    const int gid = lane >> 2, tig = lane & 3;
#pragma unroll
    for (int mt = 0; mt < 4; mt++) {
        int row0 = bm * 128 + wm * 64 + mt * 16 + gid;
#pragma unroll
        for (int nt = 0; nt < 4; nt++) {
            int col = bn * 128 + wn * 32 + nt * 8 + tig * 2;
            float b0 = bias1 ? bias1[col] : 0.f;
            float b1 = bias1 ? bias1[col + 1] : 0.f;
            if (bias2) { b0 += bias2[col]; b1 += bias2[col + 1]; }
            *(float2*)(C + (size_t)row0 * ldc + col) =
                make_float2(acc[mt][nt][0] + b0, acc[mt][nt][1] + b1);
            *(float2*)(C + (size_t)(row0 + 8) * ldc + col) =
                make_float2(acc[mt][nt][2] + b0, acc[mt][nt][3] + b1);
        }
    }
}

// ---------------------------------------------------------------------------
// Fused 2-layer persistent LSTM, wavefront pipeline (R14-proven, unchanged).
// Round r: layer0 t=r (r<128); layer1 t=r-1 (r>=1).
// smem: W_hh0 | W_ih1 | W_hh1 static (192KB) + 2 streams x 2 slots x 8KB.
// ---------------------------------------------------------------------------
__global__ __launch_bounds__(256, 1)
void lstm_fused(const float* __restrict__ xproj,    // [T*B][4H] layer0
                const __half* __restrict__ w0,      // W_hh0 hi [4H][1024]
                const __half* __restrict__ w1x,     // W_ih1 hi [4H][1024]
                const __half* __restrict__ w1h,     // W_hh1 hi [4H][1024]
                const float* __restrict__ c0,       // [2][B][H]
                const float* __restrict__ b_ih,     // [2][4H]
                const float* __restrict__ b_hh,     // [2][4H]
                const __half* __restrict__ h0a,     // [2][B][1024] hi
                __half* __restrict__ y0,            // [T*B][1024] hi
                __half* __restrict__ y1,            // [T*B][1024] hi
                float* __restrict__ outs) {         // hs[2][B][H], cs[2][B][H]
    extern __shared__ char dsm[];
    __shared__ unsigned s_base;

    const int tid  = threadIdx.x;
    const int blk  = blockIdx.x;
    const int n0   = blk * 8;
    const int wid  = tid >> 5;
    const int lane = tid & 31;
    const int l7   = lane & 7;
    const int l16  = lane >> 4;
    const int g2   = (lane >> 3) & 3;
    const int gid  = lane >> 2;
    const int tig  = lane & 3;
    const int mt   = wid >> 2;          // batch half
    const int nt   = wid & 3;           // gate
    const int b2   = tid >> 3;          // phase2 batch
    const int u2   = tid & 7;           // phase2 unit
    const uint32_t smb = smem_u32(dsm);

    // load 3 weight slices (32 rows x 1024 each) into swizzled chunk layout
    for (int idx = tid; idx < 3 * 4096; idx += 256) {
        int m   = idx >> 12;
        int rem = idx & 4095;
        int ci  = rem >> 8;
        int rr  = (rem >> 3) & 31;
        int c   = rem & 7;
        uint32_t dst = (uint32_t)(m * 65536 + ci * 4096 + rr * 128
                                  + ((c ^ (rr & 7)) << 4));
        int gr = (rr >> 3) * H_ + n0 + (rr & 7);
        const __half* src = (m == 0 ? w0 : (m == 1 ? w1x : w1h))
                          + (size_t)gr * H_ + ci * 64 + c * 8;
        *(float4*)(dsm + dst) = *(const float4*)src;
    }

    if (tid == 0) s_base = *(volatile unsigned*)&g_flags[blk * 32];

    float c_reg0 = c0[b2 * H_ + n0 + u2];
    float c_reg1 = c0[BH + b2 * H_ + n0 + u2];
    float bi1[4];
#pragma unroll
    for (int g = 0; g < 4; g++)
        bi1[g] = b_ih[G4H + g * H_ + n0 + u2] + b_hh[G4H + g * H_ + n0 + u2];

    __syncthreads();
    const unsigned base = s_base;

    const uint32_t aRow128 = (uint32_t)((mt * 16 + l7 + ((lane >> 3) & 1) * 8) * 128);
    const uint32_t bRow128 = (uint32_t)((nt * 8 + l7) * 128);

    for (int r = 0; r <= T_; ++r) {
        const __half* Asrc = (r == 0) ? h0a : y0 + (size_t)(r - 1) * B_ * H_;
        const __half* Bsrc = (r <= 1) ? (h0a + (size_t)B_ * H_)
                                      : y1 + (size_t)(r - 2) * B_ * H_;

        // prefetch xproj0 gate values (clamped at r=T_, discarded)
        int tx = (r < T_) ? r : (T_ - 1);
        const float* xp = xproj + ((size_t)tx * B_ + b2) * G4H + n0 + u2;
        float xpi = __ldcg(xp);
        float xpf = __ldcg(xp + H_);
        float xpg = __ldcg(xp + 2 * H_);
        float xpo = __ldcg(xp + 3 * H_);

        auto issue_slot = [&](int i) {
            int k0 = i * 128;
            int row = tid >> 3, c = tid & 7;
            uint32_t sw = (uint32_t)(row * 128 + ((c ^ (row & 7)) << 4));
            uint32_t sbA = smb + SLOTS_OFF + (uint32_t)((i & 1) * 8192);
            uint32_t sbB = sbA + 16384u;
#pragma unroll
            for (int cc = 0; cc < 2; cc++) {
                cp_async16(sbA + cc * 4096 + sw,
                           Asrc + (size_t)row * H_ + k0 + cc * 64 + c * 8);
                cp_async16(sbB + cc * 4096 + sw,
                           Bsrc + (size_t)row * H_ + k0 + cc * 64 + c * 8);
            }
            cp_commit();
        };

        float acc0[4] = {0.f, 0.f, 0.f, 0.f};
        float acc1[4] = {0.f, 0.f, 0.f, 0.f};

        issue_slot(0); issue_slot(1);

#pragma unroll 1
        for (int i = 0; i < 8; i++) {
            if (i < 7) cp_wait<1>(); else cp_wait<0>();
            __syncthreads();

            uint32_t slotA = smb + SLOTS_OFF + (uint32_t)((i & 1) * 8192);
            uint32_t slotB = slotA + 16384u;
            int ciBase = i * 2;
#pragma unroll
            for (int cc = 0; cc < 2; cc++) {
                uint32_t wB0  = smb + (uint32_t)((ciBase + cc) * 4096);
                uint32_t wB1x = wB0 + 65536u;
                uint32_t wB1h = wB0 + 131072u;
                uint32_t hA = slotA + (uint32_t)(cc * 4096);
                uint32_t hB = slotB + (uint32_t)(cc * 4096);
#pragma unroll
                for (int kq2 = 0; kq2 < 2; kq2++) {
                    uint32_t bOff = bRow128 + (uint32_t)((((kq2 * 4 + g2) ^ l7)) << 4);
                    uint32_t aO0  = (uint32_t)((((kq2 * 4 + l16) ^ l7)) << 4);
                    uint32_t aO1  = (uint32_t)((((kq2 * 4 + 2 + l16) ^ l7)) << 4);
                    uint32_t a0[4], a1[4], bb0[4], bb1[4], w[4];
                    ldsm4a(a0, hA + aRow128 + aO0);
                    ldsm4a(a1, hA + aRow128 + aO1);
                    ldsm4a(w, wB0 + bOff);
                    mma16816(acc0, a0, w[0], w[1]);
                    mma16816(acc0, a1, w[2], w[3]);
                    ldsm4a(w, wB1x + bOff);
                    mma16816(acc1, a0, w[0], w[1]);
                    mma16816(acc1, a1, w[2], w[3]);
                    ldsm4a(bb0, hB + aRow128 + aO0);
                    ldsm4a(bb1, hB + aRow128 + aO1);
                    ldsm4a(w, wB1h + bOff);
                    mma16816(acc1, bb0, w[0], w[1]);
                    mma16816(acc1, bb1, w[2], w[3]);
                }
            }
            __syncthreads();
            if (i + 2 < 8) issue_slot(i + 2);
        }

        // gates to smem (overlay on slot region; all slot reads done)
        float* sg0 = (float*)(dsm + SLOTS_OFF);
        float* sg1 = sg0 + 1024;
        {
            int row = mt * 16 + gid;
            sg0[nt * 256 + row * 8 + tig * 2]           = acc0[0];
            sg0[nt * 256 + row * 8 + tig * 2 + 1]       = acc0[1];
            sg0[nt * 256 + (row + 8) * 8 + tig * 2]     = acc0[2];
            sg0[nt * 256 + (row + 8) * 8 + tig * 2 + 1] = acc0[3];
            sg1[nt * 256 + row * 8 + tig * 2]           = acc1[0];
            sg1[nt * 256 + row * 8 + tig * 2 + 1]       = acc1[1];
            sg1[nt * 256 + (row + 8) * 8 + tig * 2]     = acc1[2];
            sg1[nt * 256 + (row + 8) * 8 + tig * 2 + 1] = acc1[3];
        }
        __syncthreads();

        // phase 2: layer 0 (t = r)
        if (r < T_) {
            float gi = sg0[0 * 256 + b2 * 8 + u2] + xpi;
            float gf = sg0[1 * 256 + b2 * 8 + u2] + xpf;
            float gg = sg0[2 * 256 + b2 * 8 + u2] + xpg;
            float go = sg0[3 * 256 + b2 * 8 + u2] + xpo;
            float iv = sigf(gi), fv = sigf(gf), gv = tanhf(gg), ov = sigf(go);
            c_reg0 = fv * c_reg0 + iv * gv;
            float h = ov * tanhf(c_reg0);
            y0[((size_t)r * B_ + b2) * H_ + n0 + u2] = __float2half_rn(h);
            if (r == T_ - 1) {
                outs[b2 * H_ + n0 + u2]          = h;        // hs[0]
                outs[2 * BH + b2 * H_ + n0 + u2] = c_reg0;   // cs[0]
            }
        }
        // phase 2: layer 1 (t = r-1)
        if (r >= 1) {
            int t = r - 1;
            float gi = sg1[0 * 256 + b2 * 8 + u2] + bi1[0];
            float gf = sg1[1 * 256 + b2 * 8 + u2] + bi1[1];
            float gg = sg1[2 * 256 + b2 * 8 + u2] + bi1[2];
            float go = sg1[3 * 256 + b2 * 8 + u2] + bi1[3];
            float iv = sigf(gi), fv = sigf(gf), gv = tanhf(gg), ov = sigf(go);
            c_reg1 = fv * c_reg1 + iv * gv;
            float h = ov * tanhf(c_reg1);
            y1[((size_t)t * B_ + b2) * H_ + n0 + u2] = __float2half_rn(h);
            if (t == T_ - 1) {
                outs[BH + b2 * H_ + n0 + u2]     = h;        // hs[1]
                outs[3 * BH + b2 * H_ + n0 + u2] = c_reg1;   // cs[1]
            }
        }

        // distributed barrier: publish own flag, all blocks poll all flags
        __syncthreads();
        unsigned tgt = base + (unsigned)(r + 1);
        if (tid == 0) {
            __threadfence();
            *(volatile unsigned*)&g_flags[blk * 32] = tgt;
        }
        if (wid == 0) {
            volatile unsigned* fl = g_flags;
            for (;;) {
                int ok = 1;
#pragma unroll
                for (int j = 0; j < 4; j++) {
                    unsigned v = fl[(lane + 32 * j) * 32];
                    if ((int)(v - tgt) < 0) ok = 0;
                }
                if (__all_sync(0xffffffffu, ok)) break;
                __nanosleep(16);
            }
            __threadfence();
        }
        __syncthreads();
    }
}

// ---------------------------------------------------------------------------
// Launch
// ---------------------------------------------------------------------------
extern "C" void kernel_launch(void* const* d_in, const int* in_sizes, int n_in,
                              void* d_out, int out_size) {
    const int*   input = (const int*)d_in[0];
    const float* h0    = (const float*)d_in[1];
    const float* c0    = (const float*)d_in[2];
    const float* emb   = (const float*)d_in[3];
    const float* W_ih  = (const float*)d_in[4];
    const float* W_hh  = (const float*)d_in[5];
    const float* b_ih  = (const float*)d_in[6];
    const float* b_hh  = (const float*)d_in[7];
    const float* dec_W = (const float*)d_in[8];
    const float* dec_b = (const float*)d_in[9];
    float* out = (float*)d_out;

    void* p;
    cudaGetSymbolAddress(&p, g_xproj);  float* xproj = (float*)p;
    cudaGetSymbolAddress(&p, g_embhi);  __half* embhi = (__half*)p;
    cudaGetSymbolAddress(&p, g_y0);     __half* y0 = (__half*)p;
    cudaGetSymbolAddress(&p, g_y1);     __half* y1 = (__half*)p;
    cudaGetSymbolAddress(&p, g_wih0hi); __half* wih0hi = (__half*)p;
    cudaGetSymbolAddress(&p, g_wih1hi); __half* wih1hi = (__half*)p;
    cudaGetSymbolAddress(&p, g_augdec); __half* augdec = (__half*)p;
    cudaGetSymbolAddress(&p, g_whhaug); __half* whhaug = (__half*)p;
    cudaGetSymbolAddress(&p, g_h0aug);  __half* h0aug = (__half*)p;

    cudaFuncSetAttribute(gemm_fp16_mma,
                         cudaFuncAttributeMaxDynamicSharedMemorySize, GEMM_SMEM);
    cudaFuncSetAttribute(lstm_fused,
                         cudaFuncAttributeMaxDynamicSharedMemorySize, LSTM_SMEM);

    // 1) ALL prep (embed gather + every fp32->fp16 conversion) in one launch
    prep_kernel<<<PREP_BLKS, 256>>>(input, emb, dec_W, W_ih, W_hh, h0,
                                    embhi, augdec, wih0hi, wih1hi,
                                    whhaug, h0aug);

    const size_t D0 = (size_t)TB * V_;

    // 2) layer0 input projection: hi-only, K=1024
    gemm_fp16_mma<<<(G4H / 128) * 32, 256, GEMM_SMEM>>>(
        embhi, wih0hi, b_ih, b_hh, xproj, H_, H_, G4H);

    // 3) fused 2-layer recurrence (129 wavefront rounds)
    lstm_fused<<<NBLK, 256, LSTM_SMEM>>>(
        xproj, whhaug, wih1hi, whhaug + (size_t)G4H * H_,
        c0, b_ih, b_hh, h0aug, y0, y1, out + D0);

    // 4) decoder: hi-only (K=1024)
    gemm_fp16_mma<<<(V_ / 128) * 32, 256, GEMM_SMEM>>>(
        y1, augdec, dec_b, nullptr, out, H_, H_, V_);
}